// round 3
// baseline (speedup 1.0000x reference)
#include <cuda_runtime.h>
#include <cstdint>

#define NVEC 131072        // 32*64*64 vectors
#define KCB  1024          // codebook entries
#define CDIM 256           // embedding dim
#define HWSZ 4096          // H*W
#define TOTAL_ZQ 33554432  // 32*256*64*64

// ---------------- device scratch (no allocations allowed) ----------------
__device__ float              g_enorm[KCB];
__device__ float              g_znorm[NVEC];
__device__ unsigned long long g_arg[NVEC];
__device__ double             g_loss;

// ---------------- helpers ----------------
__device__ __forceinline__ unsigned long long packkey(float d, int k) {
    unsigned u = __float_as_uint(d);
    u = (u & 0x80000000u) ? ~u : (u | 0x80000000u);   // order-preserving map
    return ((unsigned long long)u << 32) | (unsigned)k;
}

// ---------------- kernel 0: init scratch ----------------
__global__ void init_kernel() {
    int i = blockIdx.x * blockDim.x + threadIdx.x;
    if (i < NVEC) g_arg[i] = 0xFFFFFFFFFFFFFFFFull;
    if (i == 0)   g_loss  = 0.0;
}

// ---------------- kernel 1: ||e_k||^2 (order-insensitive; plain fp32) ----------------
__global__ void enorm_kernel(const float* __restrict__ cb) {
    int k = blockIdx.x;
    float v = cb[(size_t)k * CDIM + threadIdx.x];
    float s = v * v;
    #pragma unroll
    for (int o = 16; o; o >>= 1) s += __shfl_xor_sync(0xFFFFFFFFu, s, o);
    __shared__ float ps[8];
    if ((threadIdx.x & 31) == 0) ps[threadIdx.x >> 5] = s;
    __syncthreads();
    if (threadIdx.x == 0) {
        float tot = 0.f;
        #pragma unroll
        for (int i = 0; i < 8; i++) tot += ps[i];
        g_enorm[k] = tot;
    }
}

// ---------------- kernel 1b: ||z_n||^2, emulating XLA:CPU (LLVM VF=4 IC=2) ----------------
// m_l = sum over i of fma(x[8i+l], x[8i+l], .)  (8 strided lanes, sequential i)
// v_l = m_l + m_{l+4};  r = (v0+v2) + (v1+v3)
__global__ __launch_bounds__(256)
void znorm_kernel(const float* __restrict__ ze) {
    int n = blockIdx.x * blockDim.x + threadIdx.x;   // n = b*HW + hw
    if (n >= NVEC) return;
    int b  = n >> 12;
    int hw = n & 4095;
    const float* p = ze + (size_t)b * CDIM * HWSZ + hw;   // x[c] = p[c*HW]

    float m[8] = {0.f,0.f,0.f,0.f,0.f,0.f,0.f,0.f};
    #pragma unroll 4
    for (int i = 0; i < 32; i++) {
        #pragma unroll
        for (int l = 0; l < 8; l++) {
            float x = p[(size_t)(8 * i + l) * HWSZ];
            m[l] = __fmaf_rn(x, x, m[l]);
        }
    }
    float v0 = __fadd_rn(m[0], m[4]);
    float v1 = __fadd_rn(m[1], m[5]);
    float v2 = __fadd_rn(m[2], m[6]);
    float v3 = __fadd_rn(m[3], m[7]);
    float w0 = __fadd_rn(v0, v2);
    float w1 = __fadd_rn(v1, v3);
    g_znorm[n] = __fadd_rn(w0, w1);
}

// ---------------- kernel 2: fused fp32 GEMM + quantized-distance argmin ----------------
// dot chain: single sequential fma over c ascending (matches Eigen gebp).
// d = fl( fl(znorm + enorm) - fl(2*dot) )  -- exact reference formula rounding.
#define TM 128
#define TN 128
#define TK 32

__global__ __launch_bounds__(256, 2)
void gemm_argmin_kernel(const float* __restrict__ ze, const float* __restrict__ cb) {
    __shared__ float As[TK][TM];
    __shared__ float Bs[TK][TN];
    __shared__ float en[TN];
    __shared__ float zn[TM];

    const int kt = blockIdx.x;        // 0..7
    const int nt = blockIdx.y;        // 0..1023
    const int t  = threadIdx.x;
    const int n0 = nt * TM;
    const int b  = n0 >> 12;
    const int hw0 = n0 & 4095;

    const float* Abase = ze + (size_t)b * CDIM * HWSZ + hw0;
    const float* Bbase = cb + (size_t)(kt * TN) * CDIM;

    if (t < TN) en[t] = g_enorm[kt * TN + t];
    if (t < TM) zn[t] = g_znorm[n0 + t];

    float acc[8][8];
    #pragma unroll
    for (int i = 0; i < 8; i++)
        #pragma unroll
        for (int j = 0; j < 8; j++) acc[i][j] = 0.f;

    const int tx = t & 15;
    const int ty = t >> 4;

    for (int kk = 0; kk < CDIM; kk += TK) {
        {
            const int r4 = (t & 31) * 4;
            const int c  = t >> 5;
            #pragma unroll
            for (int cc = 0; cc < TK; cc += 8) {
                float4 v = *reinterpret_cast<const float4*>(
                    Abase + (size_t)(kk + c + cc) * HWSZ + r4);
                *reinterpret_cast<float4*>(&As[c + cc][r4]) = v;
            }
        }
        {
            const int c4 = (t & 7) * 4;
            const int j  = t >> 3;
            #pragma unroll
            for (int jj = 0; jj < TN; jj += 32) {
                float4 v = *reinterpret_cast<const float4*>(
                    Bbase + (size_t)(j + jj) * CDIM + kk + c4);
                Bs[c4 + 0][j + jj] = v.x;
                Bs[c4 + 1][j + jj] = v.y;
                Bs[c4 + 2][j + jj] = v.z;
                Bs[c4 + 3][j + jj] = v.w;
            }
        }
        __syncthreads();
        #pragma unroll
        for (int k = 0; k < TK; k++) {
            float a[8], bb[8];
            float4 a0 = *reinterpret_cast<const float4*>(&As[k][ty * 8]);
            float4 a1 = *reinterpret_cast<const float4*>(&As[k][ty * 8 + 4]);
            float4 b0 = *reinterpret_cast<const float4*>(&Bs[k][tx * 8]);
            float4 b1 = *reinterpret_cast<const float4*>(&Bs[k][tx * 8 + 4]);
            a[0]=a0.x; a[1]=a0.y; a[2]=a0.z; a[3]=a0.w;
            a[4]=a1.x; a[5]=a1.y; a[6]=a1.z; a[7]=a1.w;
            bb[0]=b0.x; bb[1]=b0.y; bb[2]=b0.z; bb[3]=b0.w;
            bb[4]=b1.x; bb[5]=b1.y; bb[6]=b1.z; bb[7]=b1.w;
            #pragma unroll
            for (int i = 0; i < 8; i++)
                #pragma unroll
                for (int j = 0; j < 8; j++)
                    acc[i][j] = __fmaf_rn(a[i], bb[j], acc[i][j]);
        }
        __syncthreads();
    }

    // --- epilogue: d = fl(fl(zn+en) - 2*S); per-row argmin, lowest-index ties ---
    #pragma unroll
    for (int i = 0; i < 8; i++) {
        const float znr = zn[ty * 8 + i];
        unsigned long long best = 0xFFFFFFFFFFFFFFFFull;
        #pragma unroll
        for (int j = 0; j < 8; j++) {
            int kidx = kt * TN + tx * 8 + j;
            float t1 = __fadd_rn(znr, en[tx * 8 + j]);
            float t2 = __fmul_rn(2.0f, acc[i][j]);
            float d  = __fadd_rn(t1, -t2);
            unsigned long long key = packkey(d, kidx);
            if (key < best) best = key;
        }
        #pragma unroll
        for (int o = 8; o; o >>= 1) {
            unsigned long long other = __shfl_xor_sync(0xFFFFFFFFu, best, o, 16);
            if (other < best) best = other;
        }
        if (tx == 0)
            atomicMin(&g_arg[n0 + ty * 8 + i], best);
    }
}

// ---------------- kernel 3: gather z_q, write indices, accumulate loss ----------------
__global__ __launch_bounds__(256)
void gather_kernel(const float* __restrict__ ze, const float* __restrict__ cb,
                   float* __restrict__ out) {
    const int nt = blockIdx.x;
    const int n0 = nt * 128;
    const int t  = threadIdx.x;
    const int row = t & 127;
    const int ch  = t >> 7;

    __shared__ int sidx[128];
    if (t < 128) {
        unsigned long long v = g_arg[n0 + t];
        int idx = (int)(unsigned)(v & 0xFFFFFFFFu);
        sidx[t] = idx;
        out[(size_t)TOTAL_ZQ + 1 + n0 + t] = (float)idx;
    }
    __syncthreads();

    const int b = n0 >> 12;
    const int hw0 = n0 & 4095;
    const float* zb = ze  + (size_t)b * CDIM * HWSZ + hw0;
    float*       ob = out + (size_t)b * CDIM * HWSZ + hw0;
    const float* cbr = cb + (size_t)sidx[row] * CDIM;

    float lsum = 0.f;
    for (int c = ch; c < CDIM; c += 2) {
        float q = __ldg(&cbr[c]);
        float z = zb[(size_t)c * HWSZ + row];
        ob[(size_t)c * HWSZ + row] = q;
        float dd = q - z;
        lsum = fmaf(dd, dd, lsum);
    }
    #pragma unroll
    for (int o = 16; o; o >>= 1) lsum += __shfl_xor_sync(0xFFFFFFFFu, lsum, o);
    __shared__ float ps[8];
    if ((t & 31) == 0) ps[t >> 5] = lsum;
    __syncthreads();
    if (t == 0) {
        float s = 0.f;
        #pragma unroll
        for (int i = 0; i < 8; i++) s += ps[i];
        atomicAdd(&g_loss, (double)s);
    }
}

// ---------------- kernel 4: finalize loss ----------------
__global__ void finish_kernel(float* __restrict__ out) {
    out[TOTAL_ZQ] = (float)(1.25 * g_loss / (double)TOTAL_ZQ);
}

// ---------------- launch ----------------
extern "C" void kernel_launch(void* const* d_in, const int* in_sizes, int n_in,
                              void* d_out, int out_size) {
    const float* ze = (const float*)d_in[0];   // (32,256,64,64)
    const float* cb = (const float*)d_in[1];   // (1024,256)
    float* out = (float*)d_out;                // [z_q | loss | indices]

    init_kernel<<<(NVEC + 255) / 256, 256>>>();
    enorm_kernel<<<KCB, 256>>>(cb);
    znorm_kernel<<<NVEC / 256, 256>>>(ze);
    dim3 grid(8, 1024);
    gemm_argmin_kernel<<<grid, 256>>>(ze, cb);
    gather_kernel<<<1024, 256>>>(ze, cb, out);
    finish_kernel<<<1, 1>>>(out);
}

// round 4
// speedup vs baseline: 1.1415x; 1.1415x over previous
#include <cuda_runtime.h>
#include <cstdint>

#define NVEC 131072        // 32*64*64 vectors
#define KCB  1024          // codebook entries
#define CDIM 256           // embedding dim
#define HWSZ 4096          // H*W
#define TOTAL_ZQ 33554432  // 32*256*64*64

// GEMM tiling
#define TMM 128            // rows per block
#define TNN 256            // codebook cols per block
#define TKK 32             // c-chunk
#define BUF_FLOATS (TKK*TMM + TKK*TNN)   // 12288 floats = 48 KB
#define SMEM_BYTES (2 * BUF_FLOATS * 4)  // 96 KB dynamic

// ---------------- device scratch ----------------
__device__ float              g_enorm[KCB];
__device__ float              g_znorm[NVEC];
__device__ float              g_cbT[CDIM * KCB];   // transposed codebook [c][k]
__device__ unsigned long long g_arg[NVEC];
__device__ double             g_loss;

// ---------------- helpers ----------------
__device__ __forceinline__ unsigned long long packkey(float d, int k) {
    unsigned u = __float_as_uint(d);
    u = (u & 0x80000000u) ? ~u : (u | 0x80000000u);   // order-preserving map
    return ((unsigned long long)u << 32) | (unsigned)k;
}

__device__ __forceinline__ void cp_async16(uint32_t dst_smem, const void* src) {
    asm volatile("cp.async.ca.shared.global [%0], [%1], 16;\n" :: "r"(dst_smem), "l"(src));
}
__device__ __forceinline__ void cp_commit() {
    asm volatile("cp.async.commit_group;\n");
}
__device__ __forceinline__ void cp_wait_all() {
    asm volatile("cp.async.wait_group 0;\n");
}

// ---------------- kernel 0: init scratch ----------------
__global__ void init_kernel() {
    int i = blockIdx.x * blockDim.x + threadIdx.x;
    if (i < NVEC) g_arg[i] = 0xFFFFFFFFFFFFFFFFull;
    if (i == 0)   g_loss  = 0.0;
}

// ---------------- kernel 1: ||e_k||^2 + codebook transpose ----------------
__global__ void enorm_kernel(const float* __restrict__ cb) {
    int k = blockIdx.x;
    float v = cb[(size_t)k * CDIM + threadIdx.x];
    g_cbT[(size_t)threadIdx.x * KCB + k] = v;      // build cbT[c][k]
    float s = v * v;
    #pragma unroll
    for (int o = 16; o; o >>= 1) s += __shfl_xor_sync(0xFFFFFFFFu, s, o);
    __shared__ float ps[8];
    if ((threadIdx.x & 31) == 0) ps[threadIdx.x >> 5] = s;
    __syncthreads();
    if (threadIdx.x == 0) {
        float tot = 0.f;
        #pragma unroll
        for (int i = 0; i < 8; i++) tot += ps[i];
        g_enorm[k] = tot;
    }
}

// ---------------- kernel 1b: ||z_n||^2, XLA:CPU chain (VF=4 IC=2) — DO NOT TOUCH ----------------
__global__ __launch_bounds__(256)
void znorm_kernel(const float* __restrict__ ze) {
    int n = blockIdx.x * blockDim.x + threadIdx.x;
    if (n >= NVEC) return;
    int b  = n >> 12;
    int hw = n & 4095;
    const float* p = ze + (size_t)b * CDIM * HWSZ + hw;

    float m[8] = {0.f,0.f,0.f,0.f,0.f,0.f,0.f,0.f};
    #pragma unroll 4
    for (int i = 0; i < 32; i++) {
        #pragma unroll
        for (int l = 0; l < 8; l++) {
            float x = p[(size_t)(8 * i + l) * HWSZ];
            m[l] = __fmaf_rn(x, x, m[l]);
        }
    }
    float v0 = __fadd_rn(m[0], m[4]);
    float v1 = __fadd_rn(m[1], m[5]);
    float v2 = __fadd_rn(m[2], m[6]);
    float v3 = __fadd_rn(m[3], m[7]);
    float w0 = __fadd_rn(v0, v2);
    float w1 = __fadd_rn(v1, v3);
    g_znorm[n] = __fadd_rn(w0, w1);
}

// ---------------- kernel 2: fused fp32 GEMM (128x256 tile) + argmin ----------------
// Accumulation per output: single sequential fma chain over c = 0..255 ascending
// (tile order ascending, k ascending) — identical to the verified-exact R3 chain.
__global__ __launch_bounds__(256, 1)
void gemm_argmin_kernel(const float* __restrict__ ze) {
    extern __shared__ float smem[];
    __shared__ float en[TNN];
    __shared__ float zn[TMM];

    const int kt = blockIdx.x;        // 0..3  (codebook tile)
    const int nt = blockIdx.y;        // 0..1023
    const int t  = threadIdx.x;
    const int n0 = nt * TMM;
    const int b  = n0 >> 12;
    const int hw0 = n0 & 4095;
    const int ktBase = kt * TNN;

    const float* Abase = ze + (size_t)b * CDIM * HWSZ + hw0;
    const float* Bbase = g_cbT + ktBase;          // [c*KCB + j]

    if (t < TNN) en[t] = g_enorm[ktBase + t];
    if (t < TMM) zn[t] = g_znorm[n0 + t];

    // smem buffers
    uint32_t smem_u32 = (uint32_t)__cvta_generic_to_shared(smem);
    // buffer p: A at p*BUF, B at p*BUF + TKK*TMM

    // prologue: load tile 0
    {
        const int p = 0;
        uint32_t aBase = smem_u32 + (p * BUF_FLOATS) * 4;
        uint32_t bBase = aBase + TKK * TMM * 4;
        #pragma unroll
        for (int r = 0; r < 4; r++) {              // A: 1024 float4
            int f = t + 256 * r;
            int c = f >> 5, m4 = (f & 31) * 4;
            cp_async16(aBase + (c * TMM + m4) * 4, Abase + (size_t)c * HWSZ + m4);
        }
        #pragma unroll
        for (int r = 0; r < 8; r++) {              // B: 2048 float4
            int f = t + 256 * r;
            int c = f >> 6, j4 = (f & 63) * 4;
            cp_async16(bBase + (c * TNN + j4) * 4, Bbase + (size_t)c * KCB + j4);
        }
        cp_commit();
    }
    cp_wait_all();
    __syncthreads();

    const int tx = t & 15;            // 16 column groups
    const int ty = t >> 4;            // 16 row groups

    float acc[8][16];
    #pragma unroll
    for (int i = 0; i < 8; i++)
        #pragma unroll
        for (int j = 0; j < 16; j++) acc[i][j] = 0.f;

    #pragma unroll 1
    for (int it = 0; it < CDIM / TKK; it++) {
        const int p = it & 1;
        const float* As = smem + p * BUF_FLOATS;
        const float* Bs = As + TKK * TMM;

        // prefetch next tile into the other buffer
        if (it + 1 < CDIM / TKK) {
            const int kk = (it + 1) * TKK;
            uint32_t aBase = smem_u32 + ((p ^ 1) * BUF_FLOATS) * 4;
            uint32_t bBase = aBase + TKK * TMM * 4;
            #pragma unroll
            for (int r = 0; r < 4; r++) {
                int f = t + 256 * r;
                int c = f >> 5, m4 = (f & 31) * 4;
                cp_async16(aBase + (c * TMM + m4) * 4, Abase + (size_t)(kk + c) * HWSZ + m4);
            }
            #pragma unroll
            for (int r = 0; r < 8; r++) {
                int f = t + 256 * r;
                int c = f >> 6, j4 = (f & 63) * 4;
                cp_async16(bBase + (c * TNN + j4) * 4, Bbase + (size_t)(kk + c) * KCB + j4);
            }
            cp_commit();
        }

        // compute on current buffer
        #pragma unroll
        for (int k = 0; k < TKK; k++) {
            float4 a0 = *reinterpret_cast<const float4*>(&As[k * TMM + ty * 4]);
            float4 a1 = *reinterpret_cast<const float4*>(&As[k * TMM + ty * 4 + 64]);
            float4 b0 = *reinterpret_cast<const float4*>(&Bs[k * TNN + tx * 4]);
            float4 b1 = *reinterpret_cast<const float4*>(&Bs[k * TNN + tx * 4 + 64]);
            float4 b2 = *reinterpret_cast<const float4*>(&Bs[k * TNN + tx * 4 + 128]);
            float4 b3 = *reinterpret_cast<const float4*>(&Bs[k * TNN + tx * 4 + 192]);
            float a[8] = {a0.x,a0.y,a0.z,a0.w,a1.x,a1.y,a1.z,a1.w};
            float bb[16] = {b0.x,b0.y,b0.z,b0.w,b1.x,b1.y,b1.z,b1.w,
                            b2.x,b2.y,b2.z,b2.w,b3.x,b3.y,b3.z,b3.w};
            #pragma unroll
            for (int i = 0; i < 8; i++)
                #pragma unroll
                for (int j = 0; j < 16; j++)
                    acc[i][j] = __fmaf_rn(a[i], bb[j], acc[i][j]);
        }

        cp_wait_all();
        __syncthreads();
    }

    // --- epilogue: d = fl(fl(zn+en) - fl(2*S)); per-row argmin, lowest-index ties ---
    #pragma unroll
    for (int i = 0; i < 8; i++) {
        const int row = (i < 4) ? (ty * 4 + i) : (64 + ty * 4 + (i - 4));
        const float znr = zn[row];
        unsigned long long best = 0xFFFFFFFFFFFFFFFFull;
        #pragma unroll
        for (int j = 0; j < 16; j++) {
            const int col  = (j >> 2) * 64 + tx * 4 + (j & 3);
            const int kidx = ktBase + col;
            float t1 = __fadd_rn(znr, en[col]);
            float t2 = __fmul_rn(2.0f, acc[i][j]);
            float d  = __fadd_rn(t1, -t2);
            unsigned long long key = packkey(d, kidx);
            if (key < best) best = key;
        }
        #pragma unroll
        for (int o = 8; o; o >>= 1) {
            unsigned long long other = __shfl_xor_sync(0xFFFFFFFFu, best, o, 16);
            if (other < best) best = other;
        }
        if (tx == 0)
            atomicMin(&g_arg[n0 + row], best);
    }
}

// ---------------- kernel 3: gather z_q, write indices, accumulate loss ----------------
__global__ __launch_bounds__(256)
void gather_kernel(const float* __restrict__ ze, const float* __restrict__ cb,
                   float* __restrict__ out) {
    const int nt = blockIdx.x;
    const int n0 = nt * 128;
    const int t  = threadIdx.x;
    const int row = t & 127;
    const int ch  = t >> 7;

    __shared__ int sidx[128];
    if (t < 128) {
        unsigned long long v = g_arg[n0 + t];
        int idx = (int)(unsigned)(v & 0xFFFFFFFFu);
        sidx[t] = idx;
        out[(size_t)TOTAL_ZQ + 1 + n0 + t] = (float)idx;
    }
    __syncthreads();

    const int b = n0 >> 12;
    const int hw0 = n0 & 4095;
    const float* zb = ze  + (size_t)b * CDIM * HWSZ + hw0;
    float*       ob = out + (size_t)b * CDIM * HWSZ + hw0;
    const float* cbr = cb + (size_t)sidx[row] * CDIM;

    float lsum = 0.f;
    for (int c = ch; c < CDIM; c += 2) {
        float q = __ldg(&cbr[c]);
        float z = zb[(size_t)c * HWSZ + row];
        ob[(size_t)c * HWSZ + row] = q;
        float dd = q - z;
        lsum = fmaf(dd, dd, lsum);
    }
    #pragma unroll
    for (int o = 16; o; o >>= 1) lsum += __shfl_xor_sync(0xFFFFFFFFu, lsum, o);
    __shared__ float ps[8];
    if ((t & 31) == 0) ps[t >> 5] = lsum;
    __syncthreads();
    if (t == 0) {
        float s = 0.f;
        #pragma unroll
        for (int i = 0; i < 8; i++) s += ps[i];
        atomicAdd(&g_loss, (double)s);
    }
}

// ---------------- kernel 4: finalize loss ----------------
__global__ void finish_kernel(float* __restrict__ out) {
    out[TOTAL_ZQ] = (float)(1.25 * g_loss / (double)TOTAL_ZQ);
}

// ---------------- launch ----------------
extern "C" void kernel_launch(void* const* d_in, const int* in_sizes, int n_in,
                              void* d_out, int out_size) {
    const float* ze = (const float*)d_in[0];   // (32,256,64,64)
    const float* cb = (const float*)d_in[1];   // (1024,256)
    float* out = (float*)d_out;                // [z_q | loss | indices]

    cudaFuncSetAttribute(gemm_argmin_kernel,
                         cudaFuncAttributeMaxDynamicSharedMemorySize, SMEM_BYTES);

    init_kernel<<<(NVEC + 255) / 256, 256>>>();
    enorm_kernel<<<KCB, 256>>>(cb);
    znorm_kernel<<<NVEC / 256, 256>>>(ze);
    dim3 grid(KCB / TNN, NVEC / TMM);          // (4, 1024)
    gemm_argmin_kernel<<<grid, 256, SMEM_BYTES>>>(ze);
    gather_kernel<<<1024, 256>>>(ze, cb, out);
    finish_kernel<<<1, 1>>>(out);
}

// round 7
// speedup vs baseline: 1.7481x; 1.5315x over previous
#include <cuda_runtime.h>
#include <cuda_bf16.h>
#include <cstdint>
#include <cfloat>

#define NVEC 131072        // 32*64*64 vectors
#define KCB  1024          // codebook entries
#define CDIM 256           // embedding dim
#define HWSZ 4096          // H*W
#define TOTAL_ZQ 33554432  // 32*256*64*64
#define EPS 5e-3f
#define MAXC 32

// smem layout (bytes). Row stride 264 halves = 528 B (16B-aligned, ldmatrix conflict-free).
#define STRH 264
#define SM_AB   0                         // 128*528 = 67584   A bf16
#define BUFB    33792                     // 64*528 B per B buffer
#define SM_B    67584                     // 2 buffers -> 135168
#define SM_EN   135168                    // 1024 f32 -> 139264
#define SM_ZN   139264                    // 128 f32  -> 139776
#define SM_CNT  139776                    // 128 i32  -> 140288
#define SM_LIST 140288                    // 128*32 u16 = 8192 -> 148480
#define SM_NEED 148480                    // 4 (+pad 128)
#define SM_CMIN 148608                    // 16*256 f32 = 16384 -> 164992
#define SM_TOTAL 164992
// rescore overlay: fp32 [c][128] = 131072 B over SM_AB/SM_B region (ends 131072 < SM_EN)

// ---------------- device scratch ----------------
__device__ float              g_enorm[KCB];
__device__ float              g_znorm[NVEC];
__device__ __align__(16) __nv_bfloat16 g_cbBf[KCB * CDIM];   // 512 KB bf16 codebook
__device__ unsigned long long g_arg[NVEC];
__device__ double             g_loss;

// ---------------- helpers ----------------
__device__ __forceinline__ unsigned long long packkey(float d, int k) {
    unsigned u = __float_as_uint(d);
    u = (u & 0x80000000u) ? ~u : (u | 0x80000000u);
    return ((unsigned long long)u << 32) | (unsigned)k;
}
__device__ __forceinline__ void cp_async16(uint32_t dst, const void* src) {
    asm volatile("cp.async.ca.shared.global [%0], [%1], 16;\n" :: "r"(dst), "l"(src));
}
__device__ __forceinline__ void cp_commit() { asm volatile("cp.async.commit_group;\n"); }
__device__ __forceinline__ void cp_wait0()  { asm volatile("cp.async.wait_group 0;\n"); }
__device__ __forceinline__ void cp_wait1()  { asm volatile("cp.async.wait_group 1;\n"); }
__device__ __forceinline__ void ldsm_x4(uint32_t* r, uint32_t addr) {
    asm volatile("ldmatrix.sync.aligned.m8n8.x4.shared.b16 {%0,%1,%2,%3}, [%4];\n"
                 : "=r"(r[0]), "=r"(r[1]), "=r"(r[2]), "=r"(r[3]) : "r"(addr));
}
__device__ __forceinline__ void mma_bf16(float* d, const uint32_t* a, const uint32_t* b) {
    asm volatile(
        "mma.sync.aligned.m16n8k16.row.col.f32.bf16.bf16.f32 "
        "{%0,%1,%2,%3}, {%4,%5,%6,%7}, {%8,%9}, {%0,%1,%2,%3};\n"
        : "+f"(d[0]), "+f"(d[1]), "+f"(d[2]), "+f"(d[3])
        : "r"(a[0]), "r"(a[1]), "r"(a[2]), "r"(a[3]), "r"(b[0]), "r"(b[1]));
}

// ---------------- kernel 0: init ----------------
__global__ void init_kernel() {
    if (blockIdx.x == 0 && threadIdx.x == 0) g_loss = 0.0;
}

// ---------------- kernel 1: ||e_k||^2 (order-insensitive) ----------------
__global__ void enorm_kernel(const float* __restrict__ cb) {
    int k = blockIdx.x;
    float v = cb[(size_t)k * CDIM + threadIdx.x];
    float s = v * v;
    #pragma unroll
    for (int o = 16; o; o >>= 1) s += __shfl_xor_sync(0xFFFFFFFFu, s, o);
    __shared__ float ps[8];
    if ((threadIdx.x & 31) == 0) ps[threadIdx.x >> 5] = s;
    __syncthreads();
    if (threadIdx.x == 0) {
        float tot = 0.f;
        #pragma unroll
        for (int i = 0; i < 8; i++) tot += ps[i];
        g_enorm[k] = tot;
    }
}

// ---------------- kernel 1b: ||z_n||^2, XLA:CPU chain (VF=4 IC=2) — VERIFIED, DO NOT TOUCH ----------------
__global__ __launch_bounds__(256)
void znorm_kernel(const float* __restrict__ ze) {
    int n = blockIdx.x * blockDim.x + threadIdx.x;
    if (n >= NVEC) return;
    int b  = n >> 12;
    int hw = n & 4095;
    const float* p = ze + (size_t)b * CDIM * HWSZ + hw;
    float m[8] = {0.f,0.f,0.f,0.f,0.f,0.f,0.f,0.f};
    #pragma unroll 4
    for (int i = 0; i < 32; i++) {
        #pragma unroll
        for (int l = 0; l < 8; l++) {
            float x = p[(size_t)(8 * i + l) * HWSZ];
            m[l] = __fmaf_rn(x, x, m[l]);
        }
    }
    float v0 = __fadd_rn(m[0], m[4]);
    float v1 = __fadd_rn(m[1], m[5]);
    float v2 = __fadd_rn(m[2], m[6]);
    float v3 = __fadd_rn(m[3], m[7]);
    float w0 = __fadd_rn(v0, v2);
    float w1 = __fadd_rn(v1, v3);
    g_znorm[n] = __fadd_rn(w0, w1);
}

// ---------------- kernel 2: convert codebook to bf16 ----------------
__global__ void pack_cb_kernel(const float* __restrict__ cb) {
    int i = blockIdx.x * blockDim.x + threadIdx.x;   // < KCB*CDIM
    g_cbBf[i] = __float2bfloat16(cb[i]);
}

// ---------------- B-chunk prefetch: 64 codes x 256 k bf16 into padded smem ----------------
__device__ __forceinline__ void prefetch_cb(uint32_t sb, int buf, int chunk, int t) {
    const __nv_bfloat16* src = g_cbBf + (size_t)chunk * 64 * CDIM;
    uint32_t dst = sb + SM_B + buf * BUFB;
    #pragma unroll
    for (int i = 0; i < 8; i++) {
        int idx = t + 256 * i;               // 0..2047
        int row = idx >> 5, ch = idx & 31;
        cp_async16(dst + row * 528 + ch * 16, src + row * CDIM + ch * 8);
    }
    cp_commit();
}

// ---------------- kernel 3: HMMA screening + exact rescore ----------------
__global__ __launch_bounds__(256, 1)
void screen_kernel(const float* __restrict__ ze, const float* __restrict__ cb) {
    extern __shared__ __align__(16) unsigned char smem[];
    const uint32_t sb = (uint32_t)__cvta_generic_to_shared(smem);
    const int t    = threadIdx.x;
    const int lane = t & 31;
    const int w    = t >> 5;
    const int m0   = w * 16;                 // warp's row base
    const int nt   = blockIdx.x;
    const int n0   = nt * 128;
    const int b    = n0 >> 12;
    const int hw0  = n0 & 4095;
    const float* Abase = ze + (size_t)b * CDIM * HWSZ + hw0;

    float* enS  = reinterpret_cast<float*>(smem + SM_EN);
    float* znS  = reinterpret_cast<float*>(smem + SM_ZN);
    int*   cntS = reinterpret_cast<int*>(smem + SM_CNT);
    unsigned short* listS = reinterpret_cast<unsigned short*>(smem + SM_LIST);
    unsigned* needS = reinterpret_cast<unsigned*>(smem + SM_NEED);
    float* cminS = reinterpret_cast<float*>(smem + SM_CMIN);
    __nv_bfloat16* ABh = reinterpret_cast<__nv_bfloat16*>(smem + SM_AB);

    // -------- prologue: en, zn, counters; A fp32->bf16 into padded smem --------
    #pragma unroll
    for (int i = 0; i < 4; i++) enS[t + 256 * i] = g_enorm[t + 256 * i];
    if (t < 128) { znS[t] = g_znorm[n0 + t]; cntS[t] = 0; }
    if (t == 0) *needS = 0;

    #pragma unroll 4
    for (int i = 0; i < 32; i++) {
        int f = t + 256 * i;
        int c = f >> 5, r4 = (f & 31) * 4;
        float4 v = *reinterpret_cast<const float4*>(Abase + (size_t)c * HWSZ + r4);
        ABh[(r4 + 0) * STRH + c] = __float2bfloat16(v.x);
        ABh[(r4 + 1) * STRH + c] = __float2bfloat16(v.y);
        ABh[(r4 + 2) * STRH + c] = __float2bfloat16(v.z);
        ABh[(r4 + 3) * STRH + c] = __float2bfloat16(v.w);
    }
    __syncthreads();

    prefetch_cb(sb, 0, 0, t);

    // A fragments: 16 k-steps, register-resident for the whole kernel
    uint32_t afr[16][4];
    #pragma unroll
    for (int ks = 0; ks < 16; ks++) {
        uint32_t addr = sb + SM_AB + (m0 + (lane & 15)) * 528 + ks * 32 + (lane >> 4) * 16;
        ldsm_x4(afr[ks], addr);
    }

    const float zlo = znS[m0 + (lane >> 2)];
    const float zhi = znS[m0 + 8 + (lane >> 2)];
    const int   c0  = (lane & 3) * 2;
    const int   rlo = m0 + (lane >> 2);
    const int   rhi = rlo + 8;
    float mlo = FLT_MAX, mhi = FLT_MAX;

    // -------- pass 0: all 16 chunks, per-row min + per-chunk min --------
    #pragma unroll 1
    for (int chunk = 0; chunk < 16; chunk++) {
        if (chunk + 1 < 16) { prefetch_cb(sb, (chunk + 1) & 1, chunk + 1, t); cp_wait1(); }
        else cp_wait0();
        __syncthreads();
        const uint32_t bb = sb + SM_B + (chunk & 1) * BUFB;
        float cm = FLT_MAX;
        #pragma unroll
        for (int ntl = 0; ntl < 8; ntl++) {
            float d[4] = {0.f, 0.f, 0.f, 0.f};
            uint32_t baddr = bb + (ntl * 8 + (lane & 7)) * 528 + (lane >> 3) * 16;
            #pragma unroll
            for (int kp = 0; kp < 8; kp++) {
                uint32_t br[4];
                ldsm_x4(br, baddr + kp * 64);
                mma_bf16(d, afr[2 * kp], br);
                mma_bf16(d, afr[2 * kp + 1], br + 2);
            }
            int kb = chunk * 64 + ntl * 8 + c0;
            float e0 = enS[kb], e1 = enS[kb + 1];
            float d00 = __fadd_rn(__fadd_rn(zlo, e0), -__fmul_rn(2.f, d[0]));
            float d01 = __fadd_rn(__fadd_rn(zlo, e1), -__fmul_rn(2.f, d[1]));
            float d10 = __fadd_rn(__fadd_rn(zhi, e0), -__fmul_rn(2.f, d[2]));
            float d11 = __fadd_rn(__fadd_rn(zhi, e1), -__fmul_rn(2.f, d[3]));
            mlo = fminf(mlo, fminf(d00, d01));
            mhi = fminf(mhi, fminf(d10, d11));
            cm  = fminf(cm, fminf(fminf(d00, d01), fminf(d10, d11)));
        }
        cminS[chunk * 256 + t] = cm;
        __syncthreads();
    }

    // -------- per-row thresholds + needed-chunk mask --------
    #pragma unroll
    for (int o = 1; o <= 2; o <<= 1) {
        mlo = fminf(mlo, __shfl_xor_sync(0xFFFFFFFFu, mlo, o));
        mhi = fminf(mhi, __shfl_xor_sync(0xFFFFFFFFu, mhi, o));
    }
    const float thrlo = mlo + EPS, thrhi = mhi + EPS;
    const float thrmax = fmaxf(thrlo, thrhi);
    unsigned mask = 0;
    #pragma unroll
    for (int ch = 0; ch < 16; ch++)
        if (cminS[ch * 256 + t] <= thrmax) mask |= (1u << ch);
    mask = __reduce_or_sync(0xFFFFFFFFu, mask);
    if (lane == 0) atomicOr(needS, mask);
    __syncthreads();
    const unsigned need = *needS;

    int tiles[16];
    int nn = 0;
    #pragma unroll
    for (int ch = 0; ch < 16; ch++)
        if ((need >> ch) & 1) tiles[nn++] = ch;

    // -------- pass 1: candidates from needed chunks only --------
    prefetch_cb(sb, 0, tiles[0], t);
    #pragma unroll 1
    for (int idx = 0; idx < nn; idx++) {
        if (idx + 1 < nn) { prefetch_cb(sb, (idx + 1) & 1, tiles[idx + 1], t); cp_wait1(); }
        else cp_wait0();
        __syncthreads();
        const uint32_t bb = sb + SM_B + (idx & 1) * BUFB;
        const int chunk = tiles[idx];
        #pragma unroll
        for (int ntl = 0; ntl < 8; ntl++) {
            float d[4] = {0.f, 0.f, 0.f, 0.f};
            uint32_t baddr = bb + (ntl * 8 + (lane & 7)) * 528 + (lane >> 3) * 16;
            #pragma unroll
            for (int kp = 0; kp < 8; kp++) {
                uint32_t br[4];
                ldsm_x4(br, baddr + kp * 64);
                mma_bf16(d, afr[2 * kp], br);
                mma_bf16(d, afr[2 * kp + 1], br + 2);
            }
            int kb = chunk * 64 + ntl * 8 + c0;
            float e0 = enS[kb], e1 = enS[kb + 1];
            float d00 = __fadd_rn(__fadd_rn(zlo, e0), -__fmul_rn(2.f, d[0]));
            float d01 = __fadd_rn(__fadd_rn(zlo, e1), -__fmul_rn(2.f, d[1]));
            float d10 = __fadd_rn(__fadd_rn(zhi, e0), -__fmul_rn(2.f, d[2]));
            float d11 = __fadd_rn(__fadd_rn(zhi, e1), -__fmul_rn(2.f, d[3]));
            if (d00 <= thrlo) { int p = atomicAdd(&cntS[rlo], 1); if (p < MAXC) listS[rlo * MAXC + p] = (unsigned short)kb; }
            if (d01 <= thrlo) { int p = atomicAdd(&cntS[rlo], 1); if (p < MAXC) listS[rlo * MAXC + p] = (unsigned short)(kb + 1); }
            if (d10 <= thrhi) { int p = atomicAdd(&cntS[rhi], 1); if (p < MAXC) listS[rhi * MAXC + p] = (unsigned short)kb; }
            if (d11 <= thrhi) { int p = atomicAdd(&cntS[rhi], 1); if (p < MAXC) listS[rhi * MAXC + p] = (unsigned short)(kb + 1); }
        }
        __syncthreads();
    }

    // -------- rescore: exact fp32 chain (verified), lowest-index tie-break --------
    float* st2 = reinterpret_cast<float*>(smem);   // overlay [c][128]
    #pragma unroll 4
    for (int i = 0; i < 32; i++) {
        int f = t + 256 * i;
        int c = f >> 5, r4 = (f & 31) * 4;
        float4 v = *reinterpret_cast<const float4*>(Abase + (size_t)c * HWSZ + r4);
        *reinterpret_cast<float4*>(&st2[c * 128 + r4]) = v;
    }
    __syncthreads();

    if (t < 128) {
        const float znr = znS[t];
        int nc = cntS[t];
        if (nc > MAXC) nc = MAXC;
        unsigned long long best = 0xFFFFFFFFFFFFFFFFull;
        for (int ci = 0; ci < nc; ci++) {
            int k = listS[t * MAXC + ci];
            const float* brow = cb + (size_t)k * CDIM;
            float acc = 0.f;
            #pragma unroll 8
            for (int c4 = 0; c4 < 64; c4++) {
                float4 bv = __ldg(reinterpret_cast<const float4*>(brow + c4 * 4));
                acc = __fmaf_rn(st2[(c4 * 4 + 0) * 128 + t], bv.x, acc);
                acc = __fmaf_rn(st2[(c4 * 4 + 1) * 128 + t], bv.y, acc);
                acc = __fmaf_rn(st2[(c4 * 4 + 2) * 128 + t], bv.z, acc);
                acc = __fmaf_rn(st2[(c4 * 4 + 3) * 128 + t], bv.w, acc);
            }
            float t1 = __fadd_rn(znr, g_enorm[k]);
            float d  = __fadd_rn(t1, -__fmul_rn(2.0f, acc));
            unsigned long long key = packkey(d, k);
            if (key < best) best = key;
        }
        g_arg[n0 + t] = best;
    }
}

// ---------------- kernel 4: gather z_q, indices, loss — VERIFIED ----------------
__global__ __launch_bounds__(256)
void gather_kernel(const float* __restrict__ ze, const float* __restrict__ cb,
                   float* __restrict__ out) {
    const int nt = blockIdx.x;
    const int n0 = nt * 128;
    const int t  = threadIdx.x;
    const int row = t & 127;
    const int ch  = t >> 7;

    __shared__ int sidx[128];
    if (t < 128) {
        unsigned long long v = g_arg[n0 + t];
        int idx = (int)(unsigned)(v & 0xFFFFFFFFu);
        sidx[t] = idx;
        out[(size_t)TOTAL_ZQ + 1 + n0 + t] = (float)idx;
    }
    __syncthreads();

    const int b = n0 >> 12;
    const int hw0 = n0 & 4095;
    const float* zb = ze  + (size_t)b * CDIM * HWSZ + hw0;
    float*       ob = out + (size_t)b * CDIM * HWSZ + hw0;
    const float* cbr = cb + (size_t)sidx[row] * CDIM;

    float lsum = 0.f;
    for (int c = ch; c < CDIM; c += 2) {
        float q = __ldg(&cbr[c]);
        float z = zb[(size_t)c * HWSZ + row];
        ob[(size_t)c * HWSZ + row] = q;
        float dd = q - z;
        lsum = fmaf(dd, dd, lsum);
    }
    #pragma unroll
    for (int o = 16; o; o >>= 1) lsum += __shfl_xor_sync(0xFFFFFFFFu, lsum, o);
    __shared__ float ps[8];
    if ((t & 31) == 0) ps[t >> 5] = lsum;
    __syncthreads();
    if (t == 0) {
        float s = 0.f;
        #pragma unroll
        for (int i = 0; i < 8; i++) s += ps[i];
        atomicAdd(&g_loss, (double)s);
    }
}

// ---------------- kernel 5: finalize loss ----------------
__global__ void finish_kernel(float* __restrict__ out) {
    out[TOTAL_ZQ] = (float)(1.25 * g_loss / (double)TOTAL_ZQ);
}

// ---------------- launch ----------------
extern "C" void kernel_launch(void* const* d_in, const int* in_sizes, int n_in,
                              void* d_out, int out_size) {
    const float* ze = (const float*)d_in[0];   // (32,256,64,64)
    const float* cb = (const float*)d_in[1];   // (1024,256)
    float* out = (float*)d_out;                // [z_q | loss | indices]

    cudaFuncSetAttribute(screen_kernel,
                         cudaFuncAttributeMaxDynamicSharedMemorySize, SM_TOTAL);

    init_kernel<<<1, 32>>>();
    enorm_kernel<<<KCB, 256>>>(cb);
    znorm_kernel<<<NVEC / 256, 256>>>(ze);
    pack_cb_kernel<<<KCB * CDIM / 256, 256>>>(cb);
    screen_kernel<<<NVEC / 128, 256, SM_TOTAL>>>(ze, cb);
    gather_kernel<<<1024, 256>>>(ze, cb, out);
    finish_kernel<<<1, 1>>>(out);
}

// round 10
// speedup vs baseline: 1.9638x; 1.1234x over previous
#include <cuda_runtime.h>
#include <cuda_bf16.h>
#include <cstdint>
#include <cfloat>

#define NVEC 131072        // 32*64*64 vectors
#define KCB  1024          // codebook entries
#define CDIM 256           // embedding dim
#define HWSZ 4096          // H*W
#define TOTAL_ZQ 33554432  // 32*256*64*64
#define EPS 5e-3f
#define MAXC 32
#define NCHUNK 32          // 32 chunks x 32 codes
#define NSC 16             // 16 superchunks x 64 codes (skip granularity)

// smem layout (bytes). Row stride 264 halves = 528 B (16B-aligned, ldmatrix conflict-free).
// B double-buffers OVERLAY the A region (A only needed until fragments are in registers).
#define STRH 264
#define SM_AB   0                         // 128*528 = 67584  A bf16 (prologue) / B buffers (mainloop)
#define BUFB    16896                     // 32*528 B per B buffer; buf0 @0, buf1 @16896
#define SM_EN   67584                     // 1024 f32 -> 71680
#define SM_ZN   71680                     // 128 f32  -> 72192
#define SM_CNT  72192                     // 128 i32  -> 72704
#define SM_LIST 72704                     // 128*32 u16 = 8192 -> 80896
#define SM_NEED 80896                     // 4 (+pad)
#define SM_TOTAL 81024                    // 2 CTAs/SM

// ---------------- device scratch ----------------
__device__ float              g_enorm[KCB];
__device__ float              g_znorm[NVEC];
__device__ __align__(16) __nv_bfloat16 g_cbBf[KCB * CDIM];   // 512 KB bf16 codebook
__device__ unsigned long long g_arg[NVEC];
__device__ double             g_loss;

// ---------------- helpers ----------------
__device__ __forceinline__ unsigned long long packkey(float d, int k) {
    unsigned u = __float_as_uint(d);
    u = (u & 0x80000000u) ? ~u : (u | 0x80000000u);
    return ((unsigned long long)u << 32) | (unsigned)k;
}
__device__ __forceinline__ void cp_async16(uint32_t dst, const void* src) {
    asm volatile("cp.async.ca.shared.global [%0], [%1], 16;\n" :: "r"(dst), "l"(src));
}
__device__ __forceinline__ void cp_commit() { asm volatile("cp.async.commit_group;\n"); }
__device__ __forceinline__ void cp_wait0()  { asm volatile("cp.async.wait_group 0;\n"); }
__device__ __forceinline__ void cp_wait1()  { asm volatile("cp.async.wait_group 1;\n"); }
__device__ __forceinline__ void ldsm_x4(uint32_t* r, uint32_t addr) {
    asm volatile("ldmatrix.sync.aligned.m8n8.x4.shared.b16 {%0,%1,%2,%3}, [%4];\n"
                 : "=r"(r[0]), "=r"(r[1]), "=r"(r[2]), "=r"(r[3]) : "r"(addr));
}
__device__ __forceinline__ void mma_bf16(float* d, const uint32_t* a, const uint32_t* b) {
    asm volatile(
        "mma.sync.aligned.m16n8k16.row.col.f32.bf16.bf16.f32 "
        "{%0,%1,%2,%3}, {%4,%5,%6,%7}, {%8,%9}, {%0,%1,%2,%3};\n"
        : "+f"(d[0]), "+f"(d[1]), "+f"(d[2]), "+f"(d[3])
        : "r"(a[0]), "r"(a[1]), "r"(a[2]), "r"(a[3]), "r"(b[0]), "r"(b[1]));
}

// ---------------- kernel 0: init ----------------
__global__ void init_kernel() {
    if (blockIdx.x == 0 && threadIdx.x == 0) g_loss = 0.0;
}

// ---------------- kernel 1: ||e_k||^2 (order-insensitive) ----------------
__global__ void enorm_kernel(const float* __restrict__ cb) {
    int k = blockIdx.x;
    float v = cb[(size_t)k * CDIM + threadIdx.x];
    float s = v * v;
    #pragma unroll
    for (int o = 16; o; o >>= 1) s += __shfl_xor_sync(0xFFFFFFFFu, s, o);
    __shared__ float ps[8];
    if ((threadIdx.x & 31) == 0) ps[threadIdx.x >> 5] = s;
    __syncthreads();
    if (threadIdx.x == 0) {
        float tot = 0.f;
        #pragma unroll
        for (int i = 0; i < 8; i++) tot += ps[i];
        g_enorm[k] = tot;
    }
}

// ---------------- kernel 1b: ||z_n||^2, XLA:CPU chain (VF=4 IC=2) — VERIFIED, DO NOT TOUCH ----------------
__global__ __launch_bounds__(256)
void znorm_kernel(const float* __restrict__ ze) {
    int n = blockIdx.x * blockDim.x + threadIdx.x;
    if (n >= NVEC) return;
    int b  = n >> 12;
    int hw = n & 4095;
    const float* p = ze + (size_t)b * CDIM * HWSZ + hw;
    float m[8] = {0.f,0.f,0.f,0.f,0.f,0.f,0.f,0.f};
    #pragma unroll 4
    for (int i = 0; i < 32; i++) {
        #pragma unroll
        for (int l = 0; l < 8; l++) {
            float x = p[(size_t)(8 * i + l) * HWSZ];
            m[l] = __fmaf_rn(x, x, m[l]);
        }
    }
    float v0 = __fadd_rn(m[0], m[4]);
    float v1 = __fadd_rn(m[1], m[5]);
    float v2 = __fadd_rn(m[2], m[6]);
    float v3 = __fadd_rn(m[3], m[7]);
    float w0 = __fadd_rn(v0, v2);
    float w1 = __fadd_rn(v1, v3);
    g_znorm[n] = __fadd_rn(w0, w1);
}

// ---------------- kernel 2: convert codebook to bf16 ----------------
__global__ void pack_cb_kernel(const float* __restrict__ cb) {
    int i = blockIdx.x * blockDim.x + threadIdx.x;
    g_cbBf[i] = __float2bfloat16(cb[i]);
}

// ---------------- B-chunk prefetch: 32 codes x 256 k bf16 into padded smem ----------------
__device__ __forceinline__ void prefetch_cb(uint32_t sb, int buf, int chunk, int t) {
    const __nv_bfloat16* src = g_cbBf + (size_t)chunk * 32 * CDIM;
    uint32_t dst = sb + SM_AB + buf * BUFB;
    #pragma unroll
    for (int i = 0; i < 4; i++) {
        int idx = t + 256 * i;               // 0..1023
        int row = idx >> 5, ch = idx & 31;
        cp_async16(dst + row * 528 + ch * 16, src + row * CDIM + ch * 8);
    }
    cp_commit();
}

// exact rescore of one codeword (VERIFIED chain: sequential ascending-c fma)
__device__ __forceinline__ unsigned long long exact_key(
        const float* zcol, float znr, int k, const float* __restrict__ cb) {
    const float* brow = cb + (size_t)k * CDIM;
    float acc = 0.f;
    #pragma unroll 8
    for (int c4 = 0; c4 < 64; c4++) {
        float4 bv = __ldg(reinterpret_cast<const float4*>(brow + c4 * 4));
        acc = __fmaf_rn(zcol[(size_t)(c4 * 4 + 0) * HWSZ], bv.x, acc);
        acc = __fmaf_rn(zcol[(size_t)(c4 * 4 + 1) * HWSZ], bv.y, acc);
        acc = __fmaf_rn(zcol[(size_t)(c4 * 4 + 2) * HWSZ], bv.z, acc);
        acc = __fmaf_rn(zcol[(size_t)(c4 * 4 + 3) * HWSZ], bv.w, acc);
    }
    float t1 = __fadd_rn(znr, g_enorm[k]);
    float d  = __fadd_rn(t1, -__fmul_rn(2.0f, acc));
    return packkey(d, k);
}

// ---------------- kernel 3: HMMA screening + exact rescore ----------------
__global__ __launch_bounds__(256, 2)
void screen_kernel(const float* __restrict__ ze, const float* __restrict__ cb) {
    extern __shared__ __align__(16) unsigned char smem[];
    const uint32_t sb = (uint32_t)__cvta_generic_to_shared(smem);
    const int t    = threadIdx.x;
    const int lane = t & 31;
    const int w    = t >> 5;
    const int m0   = w * 16;                 // warp's row base
    const int nt   = blockIdx.x;
    const int n0   = nt * 128;
    const int b    = n0 >> 12;
    const int hw0  = n0 & 4095;
    const float* Abase = ze + (size_t)b * CDIM * HWSZ + hw0;

    float* enS  = reinterpret_cast<float*>(smem + SM_EN);
    float* znS  = reinterpret_cast<float*>(smem + SM_ZN);
    int*   cntS = reinterpret_cast<int*>(smem + SM_CNT);
    unsigned short* listS = reinterpret_cast<unsigned short*>(smem + SM_LIST);
    unsigned* needS = reinterpret_cast<unsigned*>(smem + SM_NEED);
    __nv_bfloat16* ABh = reinterpret_cast<__nv_bfloat16*>(smem + SM_AB);

    // -------- prologue: en, zn, counters; A fp32->bf16 into padded smem --------
    #pragma unroll
    for (int i = 0; i < 4; i++) enS[t + 256 * i] = g_enorm[t + 256 * i];
    if (t < 128) { znS[t] = g_znorm[n0 + t]; cntS[t] = 0; }
    if (t == 0) *needS = 0;

    #pragma unroll 4
    for (int i = 0; i < 32; i++) {
        int f = t + 256 * i;
        int c = f >> 5, r4 = (f & 31) * 4;
        float4 v = *reinterpret_cast<const float4*>(Abase + (size_t)c * HWSZ + r4);
        ABh[(r4 + 0) * STRH + c] = __float2bfloat16(v.x);
        ABh[(r4 + 1) * STRH + c] = __float2bfloat16(v.y);
        ABh[(r4 + 2) * STRH + c] = __float2bfloat16(v.z);
        ABh[(r4 + 3) * STRH + c] = __float2bfloat16(v.w);
    }
    __syncthreads();

    // A fragments: 16 k-steps, register-resident for the whole kernel
    uint32_t afr[16][4];
    #pragma unroll
    for (int ks = 0; ks < 16; ks++) {
        uint32_t addr = sb + SM_AB + (m0 + (lane & 15)) * 528 + ks * 32 + (lane >> 4) * 16;
        ldsm_x4(afr[ks], addr);
    }
    __syncthreads();                          // all fragments read before B overlays A

    prefetch_cb(sb, 0, 0, t);

    const float zlo = znS[m0 + (lane >> 2)];
    const float zhi = znS[m0 + 8 + (lane >> 2)];
    const int   c0  = (lane & 3) * 2;
    const int   rlo = m0 + (lane >> 2);
    const int   rhi = rlo + 8;
    float mlo = FLT_MAX, mhi = FLT_MAX;
    float scmin[NSC];
    #pragma unroll
    for (int i = 0; i < NSC; i++) scmin[i] = FLT_MAX;

    // -------- pass 0: all 32 chunks, per-row min + per-superchunk min --------
    #pragma unroll 1
    for (int chunk = 0; chunk < NCHUNK; chunk++) {
        if (chunk + 1 < NCHUNK) { prefetch_cb(sb, (chunk + 1) & 1, chunk + 1, t); cp_wait1(); }
        else cp_wait0();
        __syncthreads();
        const uint32_t bb = sb + SM_AB + (chunk & 1) * BUFB;
        float cm = FLT_MAX;
        #pragma unroll
        for (int ntl = 0; ntl < 4; ntl++) {
            float d0[4] = {0.f, 0.f, 0.f, 0.f};
            float d1[4] = {0.f, 0.f, 0.f, 0.f};
            uint32_t baddr = bb + (ntl * 8 + (lane & 7)) * 528 + (lane >> 3) * 16;
            #pragma unroll
            for (int kp = 0; kp < 8; kp++) {
                uint32_t br[4];
                ldsm_x4(br, baddr + kp * 64);
                float* dd = (kp & 1) ? d1 : d0;        // two independent chains
                mma_bf16(dd, afr[2 * kp], br);
                mma_bf16(dd, afr[2 * kp + 1], br + 2);
            }
            int kb = chunk * 32 + ntl * 8 + c0;
            float e0 = enS[kb], e1 = enS[kb + 1];
            float s00 = d0[0] + d1[0], s01 = d0[1] + d1[1];
            float s10 = d0[2] + d1[2], s11 = d0[3] + d1[3];
            float d00 = __fadd_rn(__fadd_rn(zlo, e0), -__fmul_rn(2.f, s00));
            float d01 = __fadd_rn(__fadd_rn(zlo, e1), -__fmul_rn(2.f, s01));
            float d10 = __fadd_rn(__fadd_rn(zhi, e0), -__fmul_rn(2.f, s10));
            float d11 = __fadd_rn(__fadd_rn(zhi, e1), -__fmul_rn(2.f, s11));
            mlo = fminf(mlo, fminf(d00, d01));
            mhi = fminf(mhi, fminf(d10, d11));
            cm  = fminf(cm, fminf(fminf(d00, d01), fminf(d10, d11)));
        }
        int sc = chunk >> 1;
        scmin[sc] = fminf(scmin[sc], cm);
        __syncthreads();
    }

    // -------- per-row thresholds + needed-superchunk mask --------
    #pragma unroll
    for (int o = 1; o <= 2; o <<= 1) {
        mlo = fminf(mlo, __shfl_xor_sync(0xFFFFFFFFu, mlo, o));
        mhi = fminf(mhi, __shfl_xor_sync(0xFFFFFFFFu, mhi, o));
    }
    const float thrlo = mlo + EPS, thrhi = mhi + EPS;
    const float thrmax = fmaxf(thrlo, thrhi);
    unsigned mask = 0;
    #pragma unroll
    for (int sc = 0; sc < NSC; sc++)
        if (scmin[sc] <= thrmax) mask |= (1u << sc);
    mask = __reduce_or_sync(0xFFFFFFFFu, mask);
    if (lane == 0) atomicOr(needS, mask);
    __syncthreads();
    const unsigned need = *needS;

    int tiles[NCHUNK];
    int nn = 0;
    #pragma unroll
    for (int sc = 0; sc < NSC; sc++)
        if ((need >> sc) & 1) { tiles[nn++] = 2 * sc; tiles[nn++] = 2 * sc + 1; }

    // -------- pass 1: candidates from needed chunks only --------
    prefetch_cb(sb, 0, tiles[0], t);
    #pragma unroll 1
    for (int idx = 0; idx < nn; idx++) {
        if (idx + 1 < nn) { prefetch_cb(sb, (idx + 1) & 1, tiles[idx + 1], t); cp_wait1(); }
        else cp_wait0();
        __syncthreads();
        const uint32_t bb = sb + SM_AB + (idx & 1) * BUFB;
        const int chunk = tiles[idx];
        #pragma unroll
        for (int ntl = 0; ntl < 4; ntl++) {
            float d0[4] = {0.f, 0.f, 0.f, 0.f};
            float d1[4] = {0.f, 0.f, 0.f, 0.f};
            uint32_t baddr = bb + (ntl * 8 + (lane & 7)) * 528 + (lane >> 3) * 16;
            #pragma unroll
            for (int kp = 0; kp < 8; kp++) {
                uint32_t br[4];
                ldsm_x4(br, baddr + kp * 64);
                float* dd = (kp & 1) ? d1 : d0;
                mma_bf16(dd, afr[2 * kp], br);
                mma_bf16(dd, afr[2 * kp + 1], br + 2);
            }
            int kb = chunk * 32 + ntl * 8 + c0;
            float e0 = enS[kb], e1 = enS[kb + 1];
            float s00 = d0[0] + d1[0], s01 = d0[1] + d1[1];
            float s10 = d0[2] + d1[2], s11 = d0[3] + d1[3];
            float d00 = __fadd_rn(__fadd_rn(zlo, e0), -__fmul_rn(2.f, s00));
            float d01 = __fadd_rn(__fadd_rn(zlo, e1), -__fmul_rn(2.f, s01));
            float d10 = __fadd_rn(__fadd_rn(zhi, e0), -__fmul_rn(2.f, s10));
            float d11 = __fadd_rn(__fadd_rn(zhi, e1), -__fmul_rn(2.f, s11));
            if (d00 <= thrlo) { int p = atomicAdd(&cntS[rlo], 1); if (p < MAXC) listS[rlo * MAXC + p] = (unsigned short)kb; }
            if (d01 <= thrlo) { int p = atomicAdd(&cntS[rlo], 1); if (p < MAXC) listS[rlo * MAXC + p] = (unsigned short)(kb + 1); }
            if (d10 <= thrhi) { int p = atomicAdd(&cntS[rhi], 1); if (p < MAXC) listS[rhi * MAXC + p] = (unsigned short)kb; }
            if (d11 <= thrhi) { int p = atomicAdd(&cntS[rhi], 1); if (p < MAXC) listS[rhi * MAXC + p] = (unsigned short)(kb + 1); }
        }
        __syncthreads();
    }

    // -------- rescore: exact fp32 chain; overflow rows fall back to FULL scan --------
    if (t < 128) {
        const float znr = znS[t];
        const int nc = cntS[t];
        const float* zcol = Abase + t;       // z[c] = zcol[c*HWSZ]
        unsigned long long best = 0xFFFFFFFFFFFFFFFFull;
        if (nc <= MAXC) {
            for (int ci = 0; ci < nc; ci++) {
                unsigned long long key = exact_key(zcol, znr, listS[t * MAXC + ci], cb);
                if (key < best) best = key;
            }
        } else {
            // candidate list overflowed (astronomically rare): exact scan of all codes
            for (int k = 0; k < KCB; k++) {
                unsigned long long key = exact_key(zcol, znr, k, cb);
                if (key < best) best = key;
            }
        }
        g_arg[n0 + t] = best;
    }
}

// ---------------- kernel 4: gather z_q, indices, loss — VERIFIED ----------------
__global__ __launch_bounds__(256)
void gather_kernel(const float* __restrict__ ze, const float* __restrict__ cb,
                   float* __restrict__ out) {
    const int nt = blockIdx.x;
    const int n0 = nt * 128;
    const int t  = threadIdx.x;
    const int row = t & 127;
    const int ch  = t >> 7;

    __shared__ int sidx[128];
    if (t < 128) {
        unsigned long long v = g_arg[n0 + t];
        int idx = (int)(unsigned)(v & 0xFFFFFFFFu);
        sidx[t] = idx;
        out[(size_t)TOTAL_ZQ + 1 + n0 + t] = (float)idx;
    }
    __syncthreads();

    const int b = n0 >> 12;
    const int hw0 = n0 & 4095;
    const float* zb = ze  + (size_t)b * CDIM * HWSZ + hw0;
    float*       ob = out + (size_t)b * CDIM * HWSZ + hw0;
    const float* cbr = cb + (size_t)sidx[row] * CDIM;

    float lsum = 0.f;
    for (int c = ch; c < CDIM; c += 2) {
        float q = __ldg(&cbr[c]);
        float z = zb[(size_t)c * HWSZ + row];
        ob[(size_t)c * HWSZ + row] = q;
        float dd = q - z;
        lsum = fmaf(dd, dd, lsum);
    }
    #pragma unroll
    for (int o = 16; o; o >>= 1) lsum += __shfl_xor_sync(0xFFFFFFFFu, lsum, o);
    __shared__ float ps[8];
    if ((t & 31) == 0) ps[t >> 5] = lsum;
    __syncthreads();
    if (t == 0) {
        float s = 0.f;
        #pragma unroll
        for (int i = 0; i < 8; i++) s += ps[i];
        atomicAdd(&g_loss, (double)s);
    }
}

// ---------------- kernel 5: finalize loss ----------------
__global__ void finish_kernel(float* __restrict__ out) {
    out[TOTAL_ZQ] = (float)(1.25 * g_loss / (double)TOTAL_ZQ);
}

// ---------------- launch ----------------
extern "C" void kernel_launch(void* const* d_in, const int* in_sizes, int n_in,
                              void* d_out, int out_size) {
    const float* ze = (const float*)d_in[0];   // (32,256,64,64)
    const float* cb = (const float*)d_in[1];   // (1024,256)
    float* out = (float*)d_out;                // [z_q | loss | indices]

    cudaFuncSetAttribute(screen_kernel,
                         cudaFuncAttributeMaxDynamicSharedMemorySize, SM_TOTAL);

    init_kernel<<<1, 32>>>();
    enorm_kernel<<<KCB, 256>>>(cb);
    znorm_kernel<<<NVEC / 256, 256>>>(ze);
    pack_cb_kernel<<<KCB * CDIM / 256, 256>>>(cb);
    screen_kernel<<<NVEC / 128, 256, SM_TOTAL>>>(ze, cb);
    gather_kernel<<<1024, 256>>>(ze, cb, out);
    finish_kernel<<<1, 1>>>(out);
}